// round 16
// baseline (speedup 1.0000x reference)
#include <cuda_runtime.h>
#include <math.h>
#include <stdint.h>

#define D_MODEL 1024
#define NHEAD   16
#define DKDIM   64
#define D_FC    4096
#define BATCH   2
#define SEQ     1024
#define EPSV    1e-6f
#define ROWS    (BATCH*SEQ)

// ---------------- static device scratch ----------------
__device__ float g_xn  [(size_t)ROWS * D_MODEL];
__device__ float g_q   [(size_t)ROWS * D_MODEL];
__device__ float g_k   [(size_t)ROWS * D_MODEL];
__device__ float g_v   [(size_t)ROWS * D_MODEL];
__device__ float g_att [(size_t)ROWS * D_MODEL];
__device__ float g_x1  [(size_t)ROWS * D_MODEL];
__device__ float g_ffh [(size_t)ROWS * D_FC];
__device__ float g_part[(size_t)6 * ROWS * D_MODEL];   // split-K partials (48MB)

#define ZSTRIDE ((size_t)ROWS * D_MODEL)

// ---------------- helpers ----------------
__device__ __forceinline__ uint32_t f2tf32(float f) {
    uint32_t u;
    asm("cvt.rna.tf32.f32 %0, %1;" : "=r"(u) : "f"(f));
    return u;
}
__device__ __forceinline__ float rtf(float f) { return __uint_as_float(f2tf32(f)); }

__device__ __forceinline__ float fexp2(float y) {
    y = fmaxf(y, -126.0f);
    float z = y + 12582912.0f;
    int   n = __float_as_int(z) - 0x4B400000;
    float f = y - (z - 12582912.0f);
    float p =              1.5403530394e-4f;
    p = fmaf(p, f, 1.3333558146e-3f);
    p = fmaf(p, f, 9.6181291076e-3f);
    p = fmaf(p, f, 5.5504108665e-2f);
    p = fmaf(p, f, 2.4022650696e-1f);
    p = fmaf(p, f, 6.9314718056e-1f);
    p = fmaf(p, f, 1.0f);
    return p * __int_as_float((n + 127) << 23);
}

__device__ __forceinline__ void mma_tf32(float* d, const uint32_t* a, const uint32_t* b) {
    asm volatile(
        "mma.sync.aligned.m16n8k8.row.col.f32.tf32.tf32.f32 "
        "{%0,%1,%2,%3}, {%4,%5,%6,%7}, {%8,%9}, {%0,%1,%2,%3};"
        : "+f"(d[0]), "+f"(d[1]), "+f"(d[2]), "+f"(d[3])
        : "r"(a[0]), "r"(a[1]), "r"(a[2]), "r"(a[3]), "r"(b[0]), "r"(b[1]));
}

__device__ __forceinline__ void cp_async16(void* smem_dst, const void* gptr) {
    uint32_t d = (uint32_t)__cvta_generic_to_shared(smem_dst);
    asm volatile("cp.async.cg.shared.global [%0], [%1], 16;" :: "r"(d), "l"(gptr));
}
#define CP_COMMIT()  asm volatile("cp.async.commit_group;")
template<int N> __device__ __forceinline__ void cp_wait() {
    asm volatile("cp.async.wait_group %0;" :: "n"(N));
}

// ---------------- block reduce ----------------
__device__ __forceinline__ float blockReduceSum(float v, float* sbuf) {
    __syncthreads();
    #pragma unroll
    for (int o = 16; o; o >>= 1) v += __shfl_down_sync(0xFFFFFFFFu, v, o);
    int lane = threadIdx.x & 31, w = threadIdx.x >> 5;
    if (lane == 0) sbuf[w] = v;
    __syncthreads();
    if (w == 0) {
        v = (lane < 8) ? sbuf[lane] : 0.0f;
        #pragma unroll
        for (int o = 4; o; o >>= 1) v += __shfl_down_sync(0xFFFFFFFFu, v, o);
        if (lane == 0) sbuf[0] = v;
    }
    __syncthreads();
    return sbuf[0];
}

// ---------------- LayerNorm (torch: ddof=1, /(std+eps)); output tf32-rounded ----
__global__ void __launch_bounds__(256) ln_kernel(const float* __restrict__ x,
                                                 const float* __restrict__ alpha,
                                                 const float* __restrict__ beta,
                                                 float* __restrict__ out) {
    __shared__ float sbuf[32];
    size_t row = blockIdx.x;
    float4 v = ((const float4*)(x + row * D_MODEL))[threadIdx.x];
    float s  = v.x + v.y + v.z + v.w;
    float sq = v.x*v.x + v.y*v.y + v.z*v.z + v.w*v.w;
    float sum   = blockReduceSum(s,  sbuf);
    float sumsq = blockReduceSum(sq, sbuf);
    float mean = sum * (1.0f / D_MODEL);
    float var  = (sumsq - sum * mean) * (1.0f / (D_MODEL - 1));
    float r = 1.0f / (sqrtf(fmaxf(var, 0.0f)) + EPSV);
    float4 a = ((const float4*)alpha)[threadIdx.x];
    float4 b = ((const float4*)beta )[threadIdx.x];
    float4 o;
    o.x = rtf(a.x * (v.x - mean) * r + b.x);
    o.y = rtf(a.y * (v.y - mean) * r + b.y);
    o.z = rtf(a.z * (v.z - mean) * r + b.z);
    o.w = rtf(a.w * (v.w - mean) * r + b.w);
    ((float4*)(out + row * D_MODEL))[threadIdx.x] = o;
}

// ---------- fused split-K reduce + residual + LayerNorm (one block per row) ----
template<int SK>
__global__ void __launch_bounds__(256) reduceLN_kernel(
    const float* __restrict__ part,
    const float* __restrict__ resid,
    const float* __restrict__ alpha,
    const float* __restrict__ beta,
    float* __restrict__ x1out,
    float* __restrict__ xnout)
{
    __shared__ float sbuf[32];
    size_t row = blockIdx.x;
    size_t i = row * 256 + threadIdx.x;
    float4 a = ((const float4*)part)[i];
    #pragma unroll
    for (int s = 1; s < SK; s++) {
        float4 b = ((const float4*)(part + (size_t)s * ZSTRIDE))[i];
        a.x += b.x; a.y += b.y; a.z += b.z; a.w += b.w;
    }
    float4 rv = ((const float4*)resid)[i];
    a.x += rv.x; a.y += rv.y; a.z += rv.z; a.w += rv.w;
    ((float4*)x1out)[i] = a;

    float s1 = a.x + a.y + a.z + a.w;
    float sq = a.x*a.x + a.y*a.y + a.z*a.z + a.w*a.w;
    float sum   = blockReduceSum(s1, sbuf);
    float sumsq = blockReduceSum(sq, sbuf);
    float mean = sum * (1.0f / D_MODEL);
    float var  = (sumsq - sum * mean) * (1.0f / (D_MODEL - 1));
    float r = 1.0f / (sqrtf(fmaxf(var, 0.0f)) + EPSV);
    float4 al = ((const float4*)alpha)[threadIdx.x];
    float4 be = ((const float4*)beta )[threadIdx.x];
    float4 o;
    o.x = rtf(al.x * (a.x - mean) * r + be.x);
    o.y = rtf(al.y * (a.y - mean) * r + be.y);
    o.z = rtf(al.z * (a.z - mean) * r + be.z);
    o.w = rtf(al.w * (a.w - mean) * r + be.w);
    ((float4*)xnout)[i] = o;
}

// ---------------- split-K reduce (final): out = sum + bias + resid ----
template<int SK>
__global__ void __launch_bounds__(256) reduce_kernel(
    const float* __restrict__ part,
    const float* __restrict__ bias,
    const float* __restrict__ resid,
    float* __restrict__ out)
{
    size_t i = (size_t)blockIdx.x * 256 + threadIdx.x;
    float4 a = ((const float4*)part)[i];
    #pragma unroll
    for (int s = 1; s < SK; s++) {
        float4 b = ((const float4*)(part + (size_t)s * ZSTRIDE))[i];
        a.x += b.x; a.y += b.y; a.z += b.z; a.w += b.w;
    }
    float4 bv = ((const float4*)bias)[i & (D_MODEL / 4 - 1)];
    a.x += bv.x; a.y += bv.y; a.z += bv.z; a.w += bv.w;
    float4 rv = ((const float4*)resid)[i];
    a.x += rv.x; a.y += rv.y; a.z += rv.z; a.w += rv.w;
    ((float4*)out)[i] = a;
}

// ---------------- QKV split-K(2) reduce: {q,k,v} = rtf(part0 + part1) ----------
__global__ void __launch_bounds__(256) qkv_reduce_kernel(
    const float* __restrict__ part,
    float* __restrict__ q, float* __restrict__ k, float* __restrict__ v)
{
    size_t i = (size_t)blockIdx.x * 256 + threadIdx.x;
    #pragma unroll
    for (int sel = 0; sel < 3; sel++) {
        const float4* p0 = (const float4*)(part + (size_t)(2 * sel)     * ZSTRIDE);
        const float4* p1 = (const float4*)(part + (size_t)(2 * sel + 1) * ZSTRIDE);
        float4 a = p0[i], b = p1[i];
        float4 o;
        o.x = rtf(a.x + b.x); o.y = rtf(a.y + b.y);
        o.z = rtf(a.z + b.z); o.w = rtf(a.w + b.w);
        float4* dst = (sel == 0) ? (float4*)q : ((sel == 1) ? (float4*)k : (float4*)v);
        dst[i] = o;
    }
}

// ---------------- tf32 GEMM (R7 engine): C = A @ B^T [+bias][relu][tf32-round] --
#define GBM 128
#define GBN 128
#define GBK 32
#define GLDK 36
#define GEMM_SMEM (2u * (GBM + GBN) * GLDK * 4u)

template<bool QKV>
__global__ void __launch_bounds__(128, 2) mma_gemm(
    const float* __restrict__ A, int lda,
    const float* __restrict__ B0, const float* __restrict__ B1, const float* __restrict__ B2,
    int ldb,
    float* __restrict__ C0, float* __restrict__ C1, float* __restrict__ C2,
    int ldc,
    const float* __restrict__ bias,
    int K, int relu, int tfout)
{
    extern __shared__ float sm[];
    float* As = sm;
    float* Bs = sm + 2 * GBM * GLDK;

    const float* B = B0;
    float* C = C0;
    int bn = blockIdx.x * GBN;
    if (QKV) {
        int sel = blockIdx.x >> 3;
        B = (sel == 0) ? B0 : ((sel == 1) ? B1 : B2);
        C = (sel == 0) ? C0 : ((sel == 1) ? C1 : C2);
        bn = (blockIdx.x & 7) * GBN;
    }
    const bool partial = (gridDim.z > 1);
    const int kbase = blockIdx.z * K;
    if (partial) C += (size_t)blockIdx.z * ZSTRIDE;

    const int bm = blockIdx.y * GBM;
    const int tid  = threadIdx.x;
    const int lane = tid & 31;
    const int warp = tid >> 5;
    const int wm0 = (warp & 1) * 64;
    const int wn0 = (warp >> 1) * 64;
    const int r = lane >> 2;
    const int c = lane & 3;

    float acc[4][8][4];
    #pragma unroll
    for (int i = 0; i < 4; i++)
        #pragma unroll
        for (int j = 0; j < 8; j++)
            #pragma unroll
            for (int q = 0; q < 4; q++) acc[i][j][q] = 0.0f;

    float4 br[8];

    auto loadA = [&](int k0, int st) {
        float* Ad = As + st * (GBM * GLDK);
        #pragma unroll
        for (int i = 0; i < 8; i++) {
            int idx = tid + i * 128;
            int m = idx >> 3, kq = (idx & 7) * 4;
            cp_async16(Ad + m * GLDK + kq, A + (size_t)(bm + m) * lda + kbase + k0 + kq);
        }
    };
    auto ldgB = [&](int k0) {
        #pragma unroll
        for (int i = 0; i < 8; i++) {
            int idx = tid + i * 128;
            int n = idx >> 3, kq = (idx & 7) * 4;
            br[i] = *(const float4*)(B + (size_t)(bn + n) * ldb + kbase + k0 + kq);
        }
    };
    auto stsB = [&](int st) {
        float* Bd = Bs + st * (GBN * GLDK);
        #pragma unroll
        for (int i = 0; i < 8; i++) {
            int idx = tid + i * 128;
            int n = idx >> 3, kq = (idx & 7) * 4;
            uint4 u;
            u.x = f2tf32(br[i].x); u.y = f2tf32(br[i].y);
            u.z = f2tf32(br[i].z); u.w = f2tf32(br[i].w);
            *(uint4*)(Bd + n * GLDK + kq) = u;
        }
    };

    auto compute = [&](int st) {
        const float* Ab = As + st * (GBM * GLDK);
        const float* Bb = Bs + st * (GBN * GLDK);
        #pragma unroll
        for (int ks = 0; ks < GBK; ks += 8) {
            uint32_t af[4][4], bf[8][2];
            #pragma unroll
            for (int mt = 0; mt < 4; mt++) {
                int m = wm0 + mt * 16 + r;
                af[mt][0] = __float_as_uint(Ab[m * GLDK + ks + c]);
                af[mt][1] = __float_as_uint(Ab[(m + 8) * GLDK + ks + c]);
                af[mt][2] = __float_as_uint(Ab[m * GLDK + ks + c + 4]);
                af[mt][3] = __float_as_uint(Ab[(m + 8) * GLDK + ks + c + 4]);
            }
            #pragma unroll
            for (int nt = 0; nt < 8; nt++) {
                int n = wn0 + nt * 8 + r;
                bf[nt][0] = __float_as_uint(Bb[n * GLDK + ks + c]);
                bf[nt][1] = __float_as_uint(Bb[n * GLDK + ks + c + 4]);
            }
            #pragma unroll
            for (int mt = 0; mt < 4; mt++)
                #pragma unroll
                for (int nt = 0; nt < 8; nt++)
                    mma_tf32(acc[mt][nt], af[mt], bf[nt]);
        }
    };

    const int kt = K / GBK;
    ldgB(0);
    stsB(0);
    loadA(0, 0);
    CP_COMMIT();
    for (int t = 0; t < kt; t++) {
        bool more = (t + 1) < kt;
        if (more) ldgB((t + 1) * GBK);
        cp_wait<0>();
        __syncthreads();
        if (more) loadA((t + 1) * GBK, (t + 1) & 1);
        CP_COMMIT();
        compute(t & 1);
        if (more) stsB((t + 1) & 1);
    }

    // epilogue
    #pragma unroll
    for (int mt = 0; mt < 4; mt++) {
        int row = bm + wm0 + mt * 16 + r;
        #pragma unroll
        for (int nt = 0; nt < 8; nt++) {
            int col = bn + wn0 + nt * 8 + c * 2;
            float2 bv = make_float2(0.f, 0.f);
            if (!partial && bias) bv = *(const float2*)(bias + col);
            #pragma unroll
            for (int half = 0; half < 2; half++) {
                int rr = row + half * 8;
                float2 o;
                o.x = acc[mt][nt][half * 2 + 0] + bv.x;
                o.y = acc[mt][nt][half * 2 + 1] + bv.y;
                if (!partial) {
                    if (relu) { o.x = fmaxf(o.x, 0.f); o.y = fmaxf(o.y, 0.f); }
                    if (tfout) { o.x = rtf(o.x); o.y = rtf(o.y); }
                }
                *(float2*)(C + (size_t)rr * ldc + col) = o;
            }
        }
    }
}

// ---------------- fused flash attention (R11: Q in registers, sync K/V loads) --
#define FLDK 68
#define FLASH_SMEM ((64*FLDK + 64*FLDK + 128*FLDK) * 4u + 64 * 4u)
#define SCL 0.18033688011112042f   /* 0.125 * log2(e) */

__global__ void __launch_bounds__(256, 2) flash_kernel(
    const float* __restrict__ Q, const float* __restrict__ Kg,
    const float* __restrict__ Vg, const int* __restrict__ mask,
    float* __restrict__ O)
{
    extern __shared__ float sm[];
    float* Ks = sm;                         // [64][FLDK]
    float* Vs = Ks + 64 * FLDK;             // [64][FLDK]
    float* Ps = Vs + 64 * FLDK;             // [128][FLDK]
    int*  msk = (int*)(Ps + 128 * FLDK);    // [64]

    const int qt = blockIdx.x;
    const int bh = blockIdx.y;
    const int b  = bh / NHEAD;
    const int h  = bh - b * NHEAD;
    const int tid  = threadIdx.x;
    const int lane = tid & 31;
    const int warp = tid >> 5;
    const int r = lane >> 2;
    const int c = lane & 3;
    const size_t rowbase = (size_t)b * SEQ + qt * 128;
    const int hcol = h * DKDIM;
    const int wr = warp * 16;

    // Q fragments: register-resident for all kv tiles (Q already tf32-rounded)
    uint32_t qf[8][4];
    {
        const float* Qp0 = Q + (rowbase + wr + r) * D_MODEL + hcol;
        const float* Qp1 = Qp0 + 8 * D_MODEL;
        #pragma unroll
        for (int k8 = 0; k8 < 8; k8++) {
            qf[k8][0] = __float_as_uint(Qp0[k8 * 8 + c]);
            qf[k8][1] = __float_as_uint(Qp1[k8 * 8 + c]);
            qf[k8][2] = __float_as_uint(Qp0[k8 * 8 + c + 4]);
            qf[k8][3] = __float_as_uint(Qp1[k8 * 8 + c + 4]);
        }
    }

    float m0 = -3.0e38f, m1 = -3.0e38f, l0 = 0.0f, l1 = 0.0f;
    float acc_o[8][4];
    #pragma unroll
    for (int nt = 0; nt < 8; nt++)
        #pragma unroll
        for (int q = 0; q < 4; q++) acc_o[nt][q] = 0.0f;

    for (int kv0 = 0; kv0 < SEQ; kv0 += 64) {
        __syncthreads();
        #pragma unroll
        for (int i = 0; i < 4; i++) {
            int idx = tid + i * 256;
            int n = idx >> 4, kq = (idx & 15) * 4;
            size_t grow = (size_t)b * SEQ + kv0 + n;
            *(float4*)(Ks + n * FLDK + kq) = *(const float4*)(Kg + grow * D_MODEL + hcol + kq);
            *(float4*)(Vs + n * FLDK + kq) = *(const float4*)(Vg + grow * D_MODEL + hcol + kq);
        }
        if (tid < 64) msk[tid] = mask[b * SEQ + kv0 + tid];
        __syncthreads();

        // ---- S = Q K^T (Q from registers) ----
        float s[8][4];
        #pragma unroll
        for (int nt = 0; nt < 8; nt++)
            #pragma unroll
            for (int q = 0; q < 4; q++) s[nt][q] = 0.0f;

        #pragma unroll
        for (int k8 = 0; k8 < 8; k8++) {
            uint32_t bf[8][2];
            #pragma unroll
            for (int nt = 0; nt < 8; nt++) {
                int n = nt * 8 + r;
                bf[nt][0] = __float_as_uint(Ks[n * FLDK + k8 * 8 + c]);
                bf[nt][1] = __float_as_uint(Ks[n * FLDK + k8 * 8 + c + 4]);
            }
            #pragma unroll
            for (int nt = 0; nt < 8; nt++) mma_tf32(s[nt], qf[k8], bf[nt]);
        }

        // ---- scale (base-2) + mask + tile max ----
        float tm0 = -3.0e38f, tm1 = -3.0e38f;
        #pragma unroll
        for (int nt = 0; nt < 8; nt++) {
            int col0 = nt * 8 + 2 * c;
            int mk0 = msk[col0], mk1 = msk[col0 + 1];
            s[nt][0] = mk0 ? s[nt][0] * SCL : -1e9f;
            s[nt][1] = mk1 ? s[nt][1] * SCL : -1e9f;
            s[nt][2] = mk0 ? s[nt][2] * SCL : -1e9f;
            s[nt][3] = mk1 ? s[nt][3] * SCL : -1e9f;
            tm0 = fmaxf(tm0, fmaxf(s[nt][0], s[nt][1]));
            tm1 = fmaxf(tm1, fmaxf(s[nt][2], s[nt][3]));
        }
        tm0 = fmaxf(tm0, __shfl_xor_sync(0xFFFFFFFFu, tm0, 1));
        tm0 = fmaxf(tm0, __shfl_xor_sync(0xFFFFFFFFu, tm0, 2));
        tm1 = fmaxf(tm1, __shfl_xor_sync(0xFFFFFFFFu, tm1, 1));
        tm1 = fmaxf(tm1, __shfl_xor_sync(0xFFFFFFFFu, tm1, 2));

        float mn0 = fmaxf(m0, tm0);
        float mn1 = fmaxf(m1, tm1);
        float f0 = fexp2(m0 - mn0);
        float f1 = fexp2(m1 - mn1);
        m0 = mn0; m1 = mn1;

        // ---- P = 2^(S-m), row sums, store P (rna) ----
        float sum0 = 0.0f, sum1 = 0.0f;
        #pragma unroll
        for (int nt = 0; nt < 8; nt++) {
            float p0 = fexp2(s[nt][0] - mn0);
            float p1 = fexp2(s[nt][1] - mn0);
            float p2 = fexp2(s[nt][2] - mn1);
            float p3 = fexp2(s[nt][3] - mn1);
            sum0 += p0 + p1; sum1 += p2 + p3;
            int col0 = nt * 8 + 2 * c;
            *(float2*)(Ps + (wr + r) * FLDK + col0)     = make_float2(rtf(p0), rtf(p1));
            *(float2*)(Ps + (wr + r + 8) * FLDK + col0) = make_float2(rtf(p2), rtf(p3));
        }
        sum0 += __shfl_xor_sync(0xFFFFFFFFu, sum0, 1);
        sum0 += __shfl_xor_sync(0xFFFFFFFFu, sum0, 2);
        sum1 += __shfl_xor_sync(0xFFFFFFFFu, sum1, 1);
        sum1 += __shfl_xor_sync(0xFFFFFFFFu, sum1, 2);
        l0 = l0 * f0 + sum0;
        l1 = l1 * f1 + sum1;

        #pragma unroll
        for (int nt = 0; nt < 8; nt++) {
            acc_o[nt][0] *= f0; acc_o[nt][1] *= f0;
            acc_o[nt][2] *= f1; acc_o[nt][3] *= f1;
        }
        __syncwarp();

        // ---- O += P V ----
        #pragma unroll
        for (int k8 = 0; k8 < 8; k8++) {
            uint32_t pf[4], vf[8][2];
            int ks = k8 * 8;
            int m = wr + r;
            pf[0] = __float_as_uint(Ps[m * FLDK + ks + c]);
            pf[1] = __float_as_uint(Ps[(m + 8) * FLDK + ks + c]);
            pf[2] = __float_as_uint(Ps[m * FLDK + ks + c + 4]);
            pf[3] = __float_as_uint(Ps[(m + 8) * FLDK + ks + c + 4]);
            #pragma unroll
            for (int nt = 0; nt < 8; nt++) {
                int n = nt * 8 + r;
                vf[nt][0] = __float_as_uint(Vs[(ks + c) * FLDK + n]);
                vf[nt][1] = __float_as_uint(Vs[(ks + c + 4) * FLDK + n]);
            }
            #pragma unroll
            for (int nt = 0; nt < 8; nt++) mma_tf32(acc_o[nt], pf, vf[nt]);
        }
    }

    float inv0 = 1.0f / l0, inv1 = 1.0f / l1;
    size_t row0 = rowbase + wr + r;
    #pragma unroll
    for (int nt = 0; nt < 8; nt++) {
        int col = nt * 8 + 2 * c;
        *(float2*)(O + row0 * D_MODEL + hcol + col) =
            make_float2(rtf(acc_o[nt][0] * inv0), rtf(acc_o[nt][1] * inv0));
        *(float2*)(O + (row0 + 8) * D_MODEL + hcol + col) =
            make_float2(rtf(acc_o[nt][2] * inv1), rtf(acc_o[nt][3] * inv1));
    }
}

// ---------------- launch ----------------
extern "C" void kernel_launch(void* const* d_in, const int* in_sizes, int n_in,
                              void* d_out, int out_size) {
    (void)in_sizes; (void)n_in; (void)out_size;
    const float* x     = (const float*)d_in[0];
    const int*   mask  = (const int*  )d_in[1];
    const float* w_q   = (const float*)d_in[2];
    const float* w_k   = (const float*)d_in[3];
    const float* w_v   = (const float*)d_in[4];
    const float* w_o   = (const float*)d_in[5];
    const float* alpha1= (const float*)d_in[6];
    const float* beta1 = (const float*)d_in[7];
    const float* alpha2= (const float*)d_in[8];
    const float* beta2 = (const float*)d_in[9];
    const float* fc1_w = (const float*)d_in[10];
    const float* fc1_b = (const float*)d_in[11];
    const float* fc2_w = (const float*)d_in[12];
    const float* fc2_b = (const float*)d_in[13];
    float* out = (float*)d_out;

    float *xn, *q, *k, *v, *att, *x1, *ffh, *part;
    cudaGetSymbolAddress((void**)&xn,  g_xn);
    cudaGetSymbolAddress((void**)&q,   g_q);
    cudaGetSymbolAddress((void**)&k,   g_k);
    cudaGetSymbolAddress((void**)&v,   g_v);
    cudaGetSymbolAddress((void**)&att, g_att);
    cudaGetSymbolAddress((void**)&x1,  g_x1);
    cudaGetSymbolAddress((void**)&ffh, g_ffh);
    cudaGetSymbolAddress((void**)&part,g_part);

    cudaFuncSetAttribute((const void*)mma_gemm<true>,
        cudaFuncAttributeMaxDynamicSharedMemorySize, GEMM_SMEM);
    cudaFuncSetAttribute((const void*)mma_gemm<false>,
        cudaFuncAttributeMaxDynamicSharedMemorySize, GEMM_SMEM);
    cudaFuncSetAttribute((const void*)flash_kernel,
        cudaFuncAttributeMaxDynamicSharedMemorySize, FLASH_SMEM);

    const int R4 = ROWS * D_MODEL / 4;

    // LN1 (tf32-rounded output)
    ln_kernel<<<ROWS, 256>>>(x, alpha1, beta1, xn);

    // fused QKV — split-K=2 (768 CTAs = 2.6 waves of half-K work vs 1.3 waves full-K)
    // partials: q -> part[0..2Z), k -> part[2Z..4Z), v -> part[4Z..6Z)
    mma_gemm<true><<<dim3(24, 16, 2), 128, GEMM_SMEM>>>(
        xn, D_MODEL, w_q, w_k, w_v, D_MODEL,
        part, part + 2 * ZSTRIDE, part + 4 * ZSTRIDE, D_MODEL,
        nullptr, D_MODEL / 2, 0, 0);
    qkv_reduce_kernel<<<R4 / 256, 256>>>(part, q, k, v);

    // fused attention
    flash_kernel<<<dim3(SEQ / 128, BATCH * NHEAD), 256, FLASH_SMEM>>>(q, k, v, mask, att);

    // x1 = x + att @ w_o^T  — split-K=2, then fused reduce+residual+LN2
    mma_gemm<false><<<dim3(8, 16, 2), 128, GEMM_SMEM>>>(
        att, D_MODEL, w_o, nullptr, nullptr, D_MODEL,
        part, nullptr, nullptr, D_MODEL, nullptr, D_MODEL / 2, 0, 0);
    reduceLN_kernel<2><<<ROWS, 256>>>(part, x, alpha2, beta2, x1, xn);

    // ffh = relu(xn @ fc1_w^T + fc1_b), tf32-rounded
    mma_gemm<false><<<dim3(32, 16), 128, GEMM_SMEM>>>(
        xn, D_MODEL, fc1_w, nullptr, nullptr, D_MODEL,
        ffh, nullptr, nullptr, D_FC, fc1_b, D_MODEL, 1, 1);

    // out = x1 + ffh @ fc2_w^T + fc2_b  — split-K=2
    mma_gemm<false><<<dim3(8, 16, 2), 128, GEMM_SMEM>>>(
        ffh, D_FC, fc2_w, nullptr, nullptr, D_FC,
        part, nullptr, nullptr, D_MODEL, nullptr, D_FC / 2, 0, 0);
    reduce_kernel<2><<<R4 / 256, 256>>>(part, fc2_b, x1, out);
}

// round 17
// speedup vs baseline: 1.0120x; 1.0120x over previous
#include <cuda_runtime.h>
#include <math.h>
#include <stdint.h>

#define D_MODEL 1024
#define NHEAD   16
#define DKDIM   64
#define D_FC    4096
#define BATCH   2
#define SEQ     1024
#define EPSV    1e-6f
#define ROWS    (BATCH*SEQ)

// ---------------- static device scratch ----------------
__device__ float g_xn  [(size_t)ROWS * D_MODEL];
__device__ float g_q   [(size_t)ROWS * D_MODEL];
__device__ float g_k   [(size_t)ROWS * D_MODEL];
__device__ float g_v   [(size_t)ROWS * D_MODEL];
__device__ float g_att [(size_t)ROWS * D_MODEL];
__device__ float g_x1  [(size_t)ROWS * D_MODEL];
__device__ float g_ffh [(size_t)ROWS * D_FC];
__device__ float g_part[(size_t)4 * ROWS * D_MODEL];

#define ZSTRIDE ((size_t)ROWS * D_MODEL)

// ---------------- helpers ----------------
__device__ __forceinline__ uint32_t f2tf32(float f) {
    uint32_t u;
    asm("cvt.rna.tf32.f32 %0, %1;" : "=r"(u) : "f"(f));
    return u;
}
__device__ __forceinline__ float rtf(float f) { return __uint_as_float(f2tf32(f)); }

__device__ __forceinline__ float fexp2(float y) {
    y = fmaxf(y, -126.0f);
    float z = y + 12582912.0f;
    int   n = __float_as_int(z) - 0x4B400000;
    float f = y - (z - 12582912.0f);
    float p =              1.5403530394e-4f;
    p = fmaf(p, f, 1.3333558146e-3f);
    p = fmaf(p, f, 9.6181291076e-3f);
    p = fmaf(p, f, 5.5504108665e-2f);
    p = fmaf(p, f, 2.4022650696e-1f);
    p = fmaf(p, f, 6.9314718056e-1f);
    p = fmaf(p, f, 1.0f);
    return p * __int_as_float((n + 127) << 23);
}

__device__ __forceinline__ void mma_tf32(float* d, const uint32_t* a, const uint32_t* b) {
    asm volatile(
        "mma.sync.aligned.m16n8k8.row.col.f32.tf32.tf32.f32 "
        "{%0,%1,%2,%3}, {%4,%5,%6,%7}, {%8,%9}, {%0,%1,%2,%3};"
        : "+f"(d[0]), "+f"(d[1]), "+f"(d[2]), "+f"(d[3])
        : "r"(a[0]), "r"(a[1]), "r"(a[2]), "r"(a[3]), "r"(b[0]), "r"(b[1]));
}

__device__ __forceinline__ void cp_async16(void* smem_dst, const void* gptr) {
    uint32_t d = (uint32_t)__cvta_generic_to_shared(smem_dst);
    asm volatile("cp.async.cg.shared.global [%0], [%1], 16;" :: "r"(d), "l"(gptr));
}
#define CP_COMMIT()  asm volatile("cp.async.commit_group;")
template<int N> __device__ __forceinline__ void cp_wait() {
    asm volatile("cp.async.wait_group %0;" :: "n"(N));
}

// ---------------- block reduce ----------------
__device__ __forceinline__ float blockReduceSum(float v, float* sbuf) {
    __syncthreads();
    #pragma unroll
    for (int o = 16; o; o >>= 1) v += __shfl_down_sync(0xFFFFFFFFu, v, o);
    int lane = threadIdx.x & 31, w = threadIdx.x >> 5;
    if (lane == 0) sbuf[w] = v;
    __syncthreads();
    if (w == 0) {
        v = (lane < 8) ? sbuf[lane] : 0.0f;
        #pragma unroll
        for (int o = 4; o; o >>= 1) v += __shfl_down_sync(0xFFFFFFFFu, v, o);
        if (lane == 0) sbuf[0] = v;
    }
    __syncthreads();
    return sbuf[0];
}

// ---------------- LayerNorm (torch: ddof=1, /(std+eps)); output tf32-rounded ----
__global__ void __launch_bounds__(256) ln_kernel(const float* __restrict__ x,
                                                 const float* __restrict__ alpha,
                                                 const float* __restrict__ beta,
                                                 float* __restrict__ out) {
    __shared__ float sbuf[32];
    size_t row = blockIdx.x;
    float4 v = ((const float4*)(x + row * D_MODEL))[threadIdx.x];
    float s  = v.x + v.y + v.z + v.w;
    float sq = v.x*v.x + v.y*v.y + v.z*v.z + v.w*v.w;
    float sum   = blockReduceSum(s,  sbuf);
    float sumsq = blockReduceSum(sq, sbuf);
    float mean = sum * (1.0f / D_MODEL);
    float var  = (sumsq - sum * mean) * (1.0f / (D_MODEL - 1));
    float r = 1.0f / (sqrtf(fmaxf(var, 0.0f)) + EPSV);
    float4 a = ((const float4*)alpha)[threadIdx.x];
    float4 b = ((const float4*)beta )[threadIdx.x];
    float4 o;
    o.x = rtf(a.x * (v.x - mean) * r + b.x);
    o.y = rtf(a.y * (v.y - mean) * r + b.y);
    o.z = rtf(a.z * (v.z - mean) * r + b.z);
    o.w = rtf(a.w * (v.w - mean) * r + b.w);
    ((float4*)(out + row * D_MODEL))[threadIdx.x] = o;
}

// ---------- fused split-K reduce + residual + LayerNorm (one block per row) ----
template<int SK>
__global__ void __launch_bounds__(256) reduceLN_kernel(
    const float* __restrict__ part,
    const float* __restrict__ resid,
    const float* __restrict__ alpha,
    const float* __restrict__ beta,
    float* __restrict__ x1out,
    float* __restrict__ xnout)
{
    __shared__ float sbuf[32];
    size_t row = blockIdx.x;
    size_t i = row * 256 + threadIdx.x;
    float4 a = ((const float4*)part)[i];
    #pragma unroll
    for (int s = 1; s < SK; s++) {
        float4 b = ((const float4*)(part + (size_t)s * ZSTRIDE))[i];
        a.x += b.x; a.y += b.y; a.z += b.z; a.w += b.w;
    }
    float4 rv = ((const float4*)resid)[i];
    a.x += rv.x; a.y += rv.y; a.z += rv.z; a.w += rv.w;
    ((float4*)x1out)[i] = a;

    float s1 = a.x + a.y + a.z + a.w;
    float sq = a.x*a.x + a.y*a.y + a.z*a.z + a.w*a.w;
    float sum   = blockReduceSum(s1, sbuf);
    float sumsq = blockReduceSum(sq, sbuf);
    float mean = sum * (1.0f / D_MODEL);
    float var  = (sumsq - sum * mean) * (1.0f / (D_MODEL - 1));
    float r = 1.0f / (sqrtf(fmaxf(var, 0.0f)) + EPSV);
    float4 al = ((const float4*)alpha)[threadIdx.x];
    float4 be = ((const float4*)beta )[threadIdx.x];
    float4 o;
    o.x = rtf(al.x * (a.x - mean) * r + be.x);
    o.y = rtf(al.y * (a.y - mean) * r + be.y);
    o.z = rtf(al.z * (a.z - mean) * r + be.z);
    o.w = rtf(al.w * (a.w - mean) * r + be.w);
    ((float4*)xnout)[i] = o;
}

// ---------------- split-K reduce (final): out = sum + bias + resid ----
template<int SK>
__global__ void __launch_bounds__(256) reduce_kernel(
    const float* __restrict__ part,
    const float* __restrict__ bias,
    const float* __restrict__ resid,
    float* __restrict__ out)
{
    size_t i = (size_t)blockIdx.x * 256 + threadIdx.x;
    float4 a = ((const float4*)part)[i];
    #pragma unroll
    for (int s = 1; s < SK; s++) {
        float4 b = ((const float4*)(part + (size_t)s * ZSTRIDE))[i];
        a.x += b.x; a.y += b.y; a.z += b.z; a.w += b.w;
    }
    float4 bv = ((const float4*)bias)[i & (D_MODEL / 4 - 1)];
    a.x += bv.x; a.y += bv.y; a.z += bv.z; a.w += bv.w;
    float4 rv = ((const float4*)resid)[i];
    a.x += rv.x; a.y += rv.y; a.z += rv.z; a.w += rv.w;
    ((float4*)out)[i] = a;
}

// ---------------- tf32 GEMM (R7 engine): C = A @ B^T [+bias][relu][tf32-round] --
#define GBM 128
#define GBN 128
#define GBK 32
#define GLDK 36
#define GEMM_SMEM (2u * (GBM + GBN) * GLDK * 4u)

template<bool QKV>
__global__ void __launch_bounds__(128, 2) mma_gemm(
    const float* __restrict__ A, int lda,
    const float* __restrict__ B0, const float* __restrict__ B1, const float* __restrict__ B2,
    int ldb,
    float* __restrict__ C0, float* __restrict__ C1, float* __restrict__ C2,
    int ldc,
    const float* __restrict__ bias,
    int K, int relu, int tfout)
{
    extern __shared__ float sm[];
    float* As = sm;
    float* Bs = sm + 2 * GBM * GLDK;

    const float* B = B0;
    float* C = C0;
    int bn = blockIdx.x * GBN;
    if (QKV) {
        int sel = blockIdx.x >> 3;
        B = (sel == 0) ? B0 : ((sel == 1) ? B1 : B2);
        C = (sel == 0) ? C0 : ((sel == 1) ? C1 : C2);
        bn = (blockIdx.x & 7) * GBN;
    }
    const bool partial = (gridDim.z > 1);
    const int kbase = blockIdx.z * K;
    if (partial) C += (size_t)blockIdx.z * ZSTRIDE;

    const int bm = blockIdx.y * GBM;
    const int tid  = threadIdx.x;
    const int lane = tid & 31;
    const int warp = tid >> 5;
    const int wm0 = (warp & 1) * 64;
    const int wn0 = (warp >> 1) * 64;
    const int r = lane >> 2;
    const int c = lane & 3;

    float acc[4][8][4];
    #pragma unroll
    for (int i = 0; i < 4; i++)
        #pragma unroll
        for (int j = 0; j < 8; j++)
            #pragma unroll
            for (int q = 0; q < 4; q++) acc[i][j][q] = 0.0f;

    float4 br[8];

    auto loadA = [&](int k0, int st) {
        float* Ad = As + st * (GBM * GLDK);
        #pragma unroll
        for (int i = 0; i < 8; i++) {
            int idx = tid + i * 128;
            int m = idx >> 3, kq = (idx & 7) * 4;
            cp_async16(Ad + m * GLDK + kq, A + (size_t)(bm + m) * lda + kbase + k0 + kq);
        }
    };
    auto ldgB = [&](int k0) {
        #pragma unroll
        for (int i = 0; i < 8; i++) {
            int idx = tid + i * 128;
            int n = idx >> 3, kq = (idx & 7) * 4;
            br[i] = *(const float4*)(B + (size_t)(bn + n) * ldb + kbase + k0 + kq);
        }
    };
    auto stsB = [&](int st) {
        float* Bd = Bs + st * (GBN * GLDK);
        #pragma unroll
        for (int i = 0; i < 8; i++) {
            int idx = tid + i * 128;
            int n = idx >> 3, kq = (idx & 7) * 4;
            uint4 u;
            u.x = f2tf32(br[i].x); u.y = f2tf32(br[i].y);
            u.z = f2tf32(br[i].z); u.w = f2tf32(br[i].w);
            *(uint4*)(Bd + n * GLDK + kq) = u;
        }
    };

    auto compute = [&](int st) {
        const float* Ab = As + st * (GBM * GLDK);
        const float* Bb = Bs + st * (GBN * GLDK);
        #pragma unroll
        for (int ks = 0; ks < GBK; ks += 8) {
            uint32_t af[4][4], bf[8][2];
            #pragma unroll
            for (int mt = 0; mt < 4; mt++) {
                int m = wm0 + mt * 16 + r;
                af[mt][0] = __float_as_uint(Ab[m * GLDK + ks + c]);
                af[mt][1] = __float_as_uint(Ab[(m + 8) * GLDK + ks + c]);
                af[mt][2] = __float_as_uint(Ab[m * GLDK + ks + c + 4]);
                af[mt][3] = __float_as_uint(Ab[(m + 8) * GLDK + ks + c + 4]);
            }
            #pragma unroll
            for (int nt = 0; nt < 8; nt++) {
                int n = wn0 + nt * 8 + r;
                bf[nt][0] = __float_as_uint(Bb[n * GLDK + ks + c]);
                bf[nt][1] = __float_as_uint(Bb[n * GLDK + ks + c + 4]);
            }
            #pragma unroll
            for (int mt = 0; mt < 4; mt++)
                #pragma unroll
                for (int nt = 0; nt < 8; nt++)
                    mma_tf32(acc[mt][nt], af[mt], bf[nt]);
        }
    };

    const int kt = K / GBK;
    ldgB(0);
    stsB(0);
    loadA(0, 0);
    CP_COMMIT();
    for (int t = 0; t < kt; t++) {
        bool more = (t + 1) < kt;
        if (more) ldgB((t + 1) * GBK);
        cp_wait<0>();
        __syncthreads();
        if (more) loadA((t + 1) * GBK, (t + 1) & 1);
        CP_COMMIT();
        compute(t & 1);
        if (more) stsB((t + 1) & 1);
    }

    // epilogue
    #pragma unroll
    for (int mt = 0; mt < 4; mt++) {
        int row = bm + wm0 + mt * 16 + r;
        #pragma unroll
        for (int nt = 0; nt < 8; nt++) {
            int col = bn + wn0 + nt * 8 + c * 2;
            float2 bv = make_float2(0.f, 0.f);
            if (!partial && bias) bv = *(const float2*)(bias + col);
            #pragma unroll
            for (int half = 0; half < 2; half++) {
                int rr = row + half * 8;
                float2 o;
                o.x = acc[mt][nt][half * 2 + 0] + bv.x;
                o.y = acc[mt][nt][half * 2 + 1] + bv.y;
                if (!partial) {
                    if (relu) { o.x = fmaxf(o.x, 0.f); o.y = fmaxf(o.y, 0.f); }
                    if (tfout) { o.x = rtf(o.x); o.y = rtf(o.y); }
                }
                *(float2*)(C + (size_t)rr * ldc + col) = o;
            }
        }
    }
}

// ---------------- fused flash attention (Q in regs, P via shuffle transpose) ---
// Synchronous K/V loads (proven structure); Ps smem buffer ELIMINATED — the S
// accumulator is permuted into P·V A-fragments with warp shuffles.
#define FLDK 68
#define FLASH_SMEM ((64*FLDK + 64*FLDK) * 4u + 64 * 4u)
#define SCL 0.18033688011112042f   /* 0.125 * log2(e) */

__global__ void __launch_bounds__(256, 2) flash_kernel(
    const float* __restrict__ Q, const float* __restrict__ Kg,
    const float* __restrict__ Vg, const int* __restrict__ mask,
    float* __restrict__ O)
{
    extern __shared__ float sm[];
    float* Ks = sm;                         // [64][FLDK]
    float* Vs = Ks + 64 * FLDK;             // [64][FLDK]
    int*  msk = (int*)(Vs + 64 * FLDK);     // [64]

    const int qt = blockIdx.x;
    const int bh = blockIdx.y;
    const int b  = bh / NHEAD;
    const int h  = bh - b * NHEAD;
    const int tid  = threadIdx.x;
    const int lane = tid & 31;
    const int warp = tid >> 5;
    const int r = lane >> 2;
    const int c = lane & 3;
    const size_t rowbase = (size_t)b * SEQ + qt * 128;
    const int hcol = h * DKDIM;
    const int wr = warp * 16;
    const int odd = c & 1;
    const int srcA = (r << 2) | (c >> 1);        // source lane for cols c
    const int srcB = srcA + 2;                   // source lane for cols c+4

    // Q fragments: register-resident for all kv tiles (Q already tf32-rounded)
    uint32_t qf[8][4];
    {
        const float* Qp0 = Q + (rowbase + wr + r) * D_MODEL + hcol;
        const float* Qp1 = Qp0 + 8 * D_MODEL;
        #pragma unroll
        for (int k8 = 0; k8 < 8; k8++) {
            qf[k8][0] = __float_as_uint(Qp0[k8 * 8 + c]);
            qf[k8][1] = __float_as_uint(Qp1[k8 * 8 + c]);
            qf[k8][2] = __float_as_uint(Qp0[k8 * 8 + c + 4]);
            qf[k8][3] = __float_as_uint(Qp1[k8 * 8 + c + 4]);
        }
    }

    float m0 = -3.0e38f, m1 = -3.0e38f, l0 = 0.0f, l1 = 0.0f;
    float acc_o[8][4];
    #pragma unroll
    for (int nt = 0; nt < 8; nt++)
        #pragma unroll
        for (int q = 0; q < 4; q++) acc_o[nt][q] = 0.0f;

    for (int kv0 = 0; kv0 < SEQ; kv0 += 64) {
        __syncthreads();
        #pragma unroll
        for (int i = 0; i < 4; i++) {
            int idx = tid + i * 256;
            int n = idx >> 4, kq = (idx & 15) * 4;
            size_t grow = (size_t)b * SEQ + kv0 + n;
            *(float4*)(Ks + n * FLDK + kq) = *(const float4*)(Kg + grow * D_MODEL + hcol + kq);
            *(float4*)(Vs + n * FLDK + kq) = *(const float4*)(Vg + grow * D_MODEL + hcol + kq);
        }
        if (tid < 64) msk[tid] = mask[b * SEQ + kv0 + tid];
        __syncthreads();

        // ---- S = Q K^T (Q from registers) ----
        float s[8][4];
        #pragma unroll
        for (int nt = 0; nt < 8; nt++)
            #pragma unroll
            for (int q = 0; q < 4; q++) s[nt][q] = 0.0f;

        #pragma unroll
        for (int k8 = 0; k8 < 8; k8++) {
            uint32_t bf[8][2];
            #pragma unroll
            for (int nt = 0; nt < 8; nt++) {
                int n = nt * 8 + r;
                bf[nt][0] = __float_as_uint(Ks[n * FLDK + k8 * 8 + c]);
                bf[nt][1] = __float_as_uint(Ks[n * FLDK + k8 * 8 + c + 4]);
            }
            #pragma unroll
            for (int nt = 0; nt < 8; nt++) mma_tf32(s[nt], qf[k8], bf[nt]);
        }

        // ---- scale (base-2) + mask + tile max ----
        float tm0 = -3.0e38f, tm1 = -3.0e38f;
        #pragma unroll
        for (int nt = 0; nt < 8; nt++) {
            int col0 = nt * 8 + 2 * c;
            int mk0 = msk[col0], mk1 = msk[col0 + 1];
            s[nt][0] = mk0 ? s[nt][0] * SCL : -1e9f;
            s[nt][1] = mk1 ? s[nt][1] * SCL : -1e9f;
            s[nt][2] = mk0 ? s[nt][2] * SCL : -1e9f;
            s[nt][3] = mk1 ? s[nt][3] * SCL : -1e9f;
            tm0 = fmaxf(tm0, fmaxf(s[nt][0], s[nt][1]));
            tm1 = fmaxf(tm1, fmaxf(s[nt][2], s[nt][3]));
        }
        tm0 = fmaxf(tm0, __shfl_xor_sync(0xFFFFFFFFu, tm0, 1));
        tm0 = fmaxf(tm0, __shfl_xor_sync(0xFFFFFFFFu, tm0, 2));
        tm1 = fmaxf(tm1, __shfl_xor_sync(0xFFFFFFFFu, tm1, 1));
        tm1 = fmaxf(tm1, __shfl_xor_sync(0xFFFFFFFFu, tm1, 2));

        float mn0 = fmaxf(m0, tm0);
        float mn1 = fmaxf(m1, tm1);
        float f0 = fexp2(m0 - mn0);
        float f1 = fexp2(m1 - mn1);
        m0 = mn0; m1 = mn1;

        // ---- P = 2^(S-m) kept in registers (rna-rounded), row sums ----
        float sum0 = 0.0f, sum1 = 0.0f;
        #pragma unroll
        for (int nt = 0; nt < 8; nt++) {
            float p0 = fexp2(s[nt][0] - mn0);
            float p1 = fexp2(s[nt][1] - mn0);
            float p2 = fexp2(s[nt][2] - mn1);
            float p3 = fexp2(s[nt][3] - mn1);
            sum0 += p0 + p1; sum1 += p2 + p3;
            s[nt][0] = rtf(p0); s[nt][1] = rtf(p1);
            s[nt][2] = rtf(p2); s[nt][3] = rtf(p3);
        }
        sum0 += __shfl_xor_sync(0xFFFFFFFFu, sum0, 1);
        sum0 += __shfl_xor_sync(0xFFFFFFFFu, sum0, 2);
        sum1 += __shfl_xor_sync(0xFFFFFFFFu, sum1, 1);
        sum1 += __shfl_xor_sync(0xFFFFFFFFu, sum1, 2);
        l0 = l0 * f0 + sum0;
        l1 = l1 * f1 + sum1;

        #pragma unroll
        for (int nt = 0; nt < 8; nt++) {
            acc_o[nt][0] *= f0; acc_o[nt][1] *= f0;
            acc_o[nt][2] *= f1; acc_o[nt][3] *= f1;
        }

        // ---- O += P V  (P fragments via warp-shuffle transpose of s) ----
        // pf[0]=(row r, col c), pf[1]=(row r+8, col c),
        // pf[2]=(row r, col c+4), pf[3]=(row r+8, col c+4), cols within tile k8.
        #pragma unroll
        for (int k8 = 0; k8 < 8; k8++) {
            float u0 = __shfl_sync(0xFFFFFFFFu, s[k8][0], srcA);
            float u1 = __shfl_sync(0xFFFFFFFFu, s[k8][1], srcA);
            float u2 = __shfl_sync(0xFFFFFFFFu, s[k8][2], srcA);
            float u3 = __shfl_sync(0xFFFFFFFFu, s[k8][3], srcA);
            float w0 = __shfl_sync(0xFFFFFFFFu, s[k8][0], srcB);
            float w1 = __shfl_sync(0xFFFFFFFFu, s[k8][1], srcB);
            float w2 = __shfl_sync(0xFFFFFFFFu, s[k8][2], srcB);
            float w3 = __shfl_sync(0xFFFFFFFFu, s[k8][3], srcB);
            uint32_t pf[4];
            pf[0] = __float_as_uint(odd ? u1 : u0);
            pf[1] = __float_as_uint(odd ? u3 : u2);
            pf[2] = __float_as_uint(odd ? w1 : w0);
            pf[3] = __float_as_uint(odd ? w3 : w2);

            uint32_t vf[8][2];
            int ks = k8 * 8;
            #pragma unroll
            for (int nt = 0; nt < 8; nt++) {
                int n = nt * 8 + r;
                vf[nt][0] = __float_as_uint(Vs[(ks + c) * FLDK + n]);
                vf[nt][1] = __float_as_uint(Vs[(ks + c + 4) * FLDK + n]);
            }
            #pragma unroll
            for (int nt = 0; nt < 8; nt++) mma_tf32(acc_o[nt], pf, vf[nt]);
        }
    }

    float inv0 = 1.0f / l0, inv1 = 1.0f / l1;
    size_t row0 = rowbase + wr + r;
    #pragma unroll
    for (int nt = 0; nt < 8; nt++) {
        int col = nt * 8 + 2 * c;
        *(float2*)(O + row0 * D_MODEL + hcol + col) =
            make_float2(rtf(acc_o[nt][0] * inv0), rtf(acc_o[nt][1] * inv0));
        *(float2*)(O + (row0 + 8) * D_MODEL + hcol + col) =
            make_float2(rtf(acc_o[nt][2] * inv1), rtf(acc_o[nt][3] * inv1));
    }
}

// ---------------- launch ----------------
extern "C" void kernel_launch(void* const* d_in, const int* in_sizes, int n_in,
                              void* d_out, int out_size) {
    (void)in_sizes; (void)n_in; (void)out_size;
    const float* x     = (const float*)d_in[0];
    const int*   mask  = (const int*  )d_in[1];
    const float* w_q   = (const float*)d_in[2];
    const float* w_k   = (const float*)d_in[3];
    const float* w_v   = (const float*)d_in[4];
    const float* w_o   = (const float*)d_in[5];
    const float* alpha1= (const float*)d_in[6];
    const float* beta1 = (const float*)d_in[7];
    const float* alpha2= (const float*)d_in[8];
    const float* beta2 = (const float*)d_in[9];
    const float* fc1_w = (const float*)d_in[10];
    const float* fc1_b = (const float*)d_in[11];
    const float* fc2_w = (const float*)d_in[12];
    const float* fc2_b = (const float*)d_in[13];
    float* out = (float*)d_out;

    float *xn, *q, *k, *v, *att, *x1, *ffh, *part;
    cudaGetSymbolAddress((void**)&xn,  g_xn);
    cudaGetSymbolAddress((void**)&q,   g_q);
    cudaGetSymbolAddress((void**)&k,   g_k);
    cudaGetSymbolAddress((void**)&v,   g_v);
    cudaGetSymbolAddress((void**)&att, g_att);
    cudaGetSymbolAddress((void**)&x1,  g_x1);
    cudaGetSymbolAddress((void**)&ffh, g_ffh);
    cudaGetSymbolAddress((void**)&part,g_part);

    cudaFuncSetAttribute((const void*)mma_gemm<true>,
        cudaFuncAttributeMaxDynamicSharedMemorySize, GEMM_SMEM);
    cudaFuncSetAttribute((const void*)mma_gemm<false>,
        cudaFuncAttributeMaxDynamicSharedMemorySize, GEMM_SMEM);
    cudaFuncSetAttribute((const void*)flash_kernel,
        cudaFuncAttributeMaxDynamicSharedMemorySize, FLASH_SMEM);

    const int R4 = ROWS * D_MODEL / 4;

    // LN1 (tf32-rounded output)
    ln_kernel<<<ROWS, 256>>>(x, alpha1, beta1, xn);

    // fused QKV (full-K, proven config)
    mma_gemm<true><<<dim3(24, 16), 128, GEMM_SMEM>>>(
        xn, D_MODEL, w_q, w_k, w_v, D_MODEL,
        q, k, v, D_MODEL, nullptr, D_MODEL, 0, 1);

    // fused attention (shuffle-transpose P)
    flash_kernel<<<dim3(SEQ / 128, BATCH * NHEAD), 256, FLASH_SMEM>>>(q, k, v, mask, att);

    // x1 = x + att @ w_o^T  — split-K=2, then fused reduce+residual+LN2
    mma_gemm<false><<<dim3(8, 16, 2), 128, GEMM_SMEM>>>(
        att, D_MODEL, w_o, nullptr, nullptr, D_MODEL,
        part, nullptr, nullptr, D_MODEL, nullptr, D_MODEL / 2, 0, 0);
    reduceLN_kernel<2><<<ROWS, 256>>>(part, x, alpha2, beta2, x1, xn);

    // ffh = relu(xn @ fc1_w^T + fc1_b), tf32-rounded
    mma_gemm<false><<<dim3(32, 16), 128, GEMM_SMEM>>>(
        xn, D_MODEL, fc1_w, nullptr, nullptr, D_MODEL,
        ffh, nullptr, nullptr, D_FC, fc1_b, D_MODEL, 1, 1);

    // out = x1 + ffh @ fc2_w^T + fc2_b  — split-K=2
    mma_gemm<false><<<dim3(8, 16, 2), 128, GEMM_SMEM>>>(
        ffh, D_FC, fc2_w, nullptr, nullptr, D_FC,
        part, nullptr, nullptr, D_MODEL, nullptr, D_FC / 2, 0, 0);
    reduce_kernel<2><<<R4 / 256, 256>>>(part, fc2_b, x1, out);
}